// round 12
// baseline (speedup 1.0000x reference)
#include <cuda_runtime.h>
#include <cuda_fp16.h>
#include <cstdint>

// ---------------- problem constants ----------------
constexpr int  B_    = 16;
constexpr int  N_    = 1024;
constexpr int  CIN   = 768;
constexpr int  H_    = 8;
constexpr int  KQ_   = 256;
constexpr int  VD_   = 512;
constexpr long MTOK  = 16384;
constexpr long QKVC  = 8192;
constexpr long NHV   = 4096;
constexpr int  DOUT  = 512;
constexpr float SCALE_ = 0.04419417382415922f;     // 512^-0.5
constexpr float EPS_   = 1e-5f;

// ---------------- scratch (device globals) ----------------
__device__ __half g_qkvh [MTOK * QKVC];
__device__ __half g_attnl[(long)B_ * H_ * N_ * N_];   // half logits
__device__ __half g_attnh[(long)B_ * H_ * N_ * N_];   // half probs
__device__ __half g_aoh  [MTOK * NHV];
__device__ __half g_vth  [(long)B_ * H_ * VD_ * N_];
__device__ __half g_xh   [MTOK * CIN];
__device__ __half g_wh   [QKVC * CIN];
__device__ __half g_pwh  [(long)DOUT * NHV];
__device__ __half g_pbh  [(long)H_ * N_ * N_];        // half pos_bias
__device__ float  g_qs[QKVC], g_qh[QKVC];
__device__ float  g_ps[DOUT], g_ph[DOUT];

// ---------------- helpers ----------------
__device__ __forceinline__ void cp16(uint32_t s, const void* g) {
    asm volatile("cp.async.cg.shared.global [%0], [%1], 16;"
                 :: "r"(s), "l"(__cvta_generic_to_global(g)));
}
__device__ __forceinline__ uint32_t smem_u32(const void* p) {
    uint32_t a;
    asm("{ .reg .u64 t; cvta.to.shared.u64 t, %1; cvt.u32.u64 %0, t; }" : "=r"(a) : "l"(p));
    return a;
}
__device__ __forceinline__ void mma_f16(float* c, const uint32_t* a, uint32_t b0, uint32_t b1) {
    asm volatile(
        "mma.sync.aligned.m16n8k16.row.col.f32.f16.f16.f32 "
        "{%0,%1,%2,%3}, {%4,%5,%6,%7}, {%8,%9}, {%0,%1,%2,%3};"
        : "+f"(c[0]), "+f"(c[1]), "+f"(c[2]), "+f"(c[3])
        : "r"(a[0]), "r"(a[1]), "r"(a[2]), "r"(a[3]), "r"(b0), "r"(b1));
}
__device__ __forceinline__ void ldsm4(uint32_t* r, uint32_t a) {
    asm volatile("ldmatrix.sync.aligned.m8n8.x4.shared.b16 {%0,%1,%2,%3}, [%4];"
                 : "=r"(r[0]), "=r"(r[1]), "=r"(r[2]), "=r"(r[3]) : "r"(a));
}

// ---------------- fp16 mma GEMM: tile 128x128, K-chunk 64, 3-stage, occ 2 -------------
// A: [M][K] K-contig half. B: [N][K] K-contig half (C = A * B^T).
// MODE 0: half(BN)  1: half(alpha*acc + half bias)  2: half(clamp(-1,1))  3: fp32 BN
constexpr int LDT   = 36;
constexpr int ROWB  = LDT * 4;              // 144 bytes per row
constexpr int CH    = 128 * LDT;
constexpr int CHB   = CH * 4;               // 18432 bytes per tile buffer
constexpr int NST   = 3;
constexpr int SMEM_BYTES = 2 * NST * CHB;   // 110592 B -> 2 CTAs/SM

template<int MODE>
__global__ __launch_bounds__(256, 2)
void hgemm_kernel(const __half* __restrict__ Aall, long lda, long aos, long ais,
                  const __half* __restrict__ Ball, long ldb, long bos, long bis,
                  void* __restrict__ Call, long ldc, long cosz, long cis,
                  int K, int zdiv,
                  const float* __restrict__ p0, const float* __restrict__ p1,
                  const __half* __restrict__ pbh,
                  float alpha, long bias_is, long ldbias)
{
    extern __shared__ uint32_t smw[];
    const uint32_t sbase = smem_u32(smw);

    const int tid = threadIdx.x;
    const int wid = tid >> 5, lane = tid & 31;
    const int wm = wid & 1, wn = wid >> 1;
    const int rg = lane >> 2, lg = lane & 3;

    const int z  = blockIdx.z;
    const int zo = z / zdiv, zi = z - zo * zdiv;
    const __half* A  = Aall + (long)zo * aos + (long)zi * ais;
    const __half* Bp = Ball + (long)zo * bos + (long)zi * bis;
    const long m0 = (long)blockIdx.y * 128;
    const long n0 = (long)blockIdx.x * 128;

    float acc[4][4][4];
#pragma unroll
    for (int i = 0; i < 4; i++)
#pragma unroll
        for (int j = 0; j < 4; j++)
#pragma unroll
            for (int q = 0; q < 4; q++) acc[i][j][q] = 0.f;

    auto load_tile = [&](const __half* src, long ld, int kc, uint32_t bufByteOff) {
        const __half* s = src + (long)kc * 64;
#pragma unroll
        for (int i = 0; i < 4; i++) {
            int idx = tid + i * 256;
            int r = idx >> 3, c = idx & 7;
            cp16(sbase + bufByteOff + (uint32_t)(r * ROWB + c * 16),
                 s + (long)r * ld + c * 8);
        }
    };

    const __half* Abase = A + m0 * lda;
    const __half* Bbase = Bp + n0 * ldb;

    const uint32_t aOff = (uint32_t)((wm * 64 + (lane & 15)) * ROWB + ((lane >> 4) & 1) * 16);
    const uint32_t bOff = (uint32_t)((wn * 32 + ((lane >> 4) & 1) * 8 + (lane & 7)) * ROWB
                                     + ((lane >> 3) & 1) * 16);

    const int nch = K >> 6;
    load_tile(Abase, lda, 0, 0);
    load_tile(Bbase, ldb, 0, NST * CHB);
    asm volatile("cp.async.commit_group;");
    load_tile(Abase, lda, 1, CHB);
    load_tile(Bbase, ldb, 1, NST * CHB + CHB);
    asm volatile("cp.async.commit_group;");

    int st = 0;
    for (int kc = 0; kc < nch; kc++) {
        if (kc + 1 < nch) asm volatile("cp.async.wait_group 1;");
        else              asm volatile("cp.async.wait_group 0;");
        __syncthreads();

        const bool pf = (kc + 2 < nch);
        int s2 = st + 2; if (s2 >= NST) s2 -= NST;
        const uint32_t aPB = sbase + (uint32_t)(s2 * CHB);
        const uint32_t bPB = sbase + (uint32_t)(NST * CHB + s2 * CHB);
        const __half* aPS = Abase + (long)(kc + 2) * 64;
        const __half* bPS = Bbase + (long)(kc + 2) * 64;

        const uint32_t aStage = sbase + st * CHB + aOff;
        const uint32_t bStage = sbase + NST * CHB + st * CHB + bOff;

        // fragments for ks = 0
        uint32_t a[4][4], bfr[2][4];
#pragma unroll
        for (int i = 0; i < 4; i++) ldsm4(a[i], aStage + i * (16 * ROWB));
        ldsm4(bfr[0], bStage);
        ldsm4(bfr[1], bStage + 16 * ROWB);

#pragma unroll
        for (int ks = 0; ks < 4; ks++) {
            // spread gmem->smem prefetch (2 cp.async per ks)
            if (pf) {
                int idx = tid + ks * 256;
                int r = idx >> 3, c = idx & 7;
                cp16(aPB + (uint32_t)(r * ROWB + c * 16), aPS + (long)r * lda + c * 8);
                cp16(bPB + (uint32_t)(r * ROWB + c * 16), bPS + (long)r * ldb + c * 8);
            }
            // j-pair 0 consumes bfr[0]
#pragma unroll
            for (int i = 0; i < 4; i++) {
                mma_f16(acc[i][0], a[i], bfr[0][0], bfr[0][1]);
                mma_f16(acc[i][1], a[i], bfr[0][2], bfr[0][3]);
            }
            if (ks < 3) ldsm4(bfr[0], bStage + (ks + 1) * 32);               // rotate in place
            // j-pair 1 consumes bfr[1]
#pragma unroll
            for (int i = 0; i < 4; i++) {
                mma_f16(acc[i][2], a[i], bfr[1][0], bfr[1][1]);
                mma_f16(acc[i][3], a[i], bfr[1][2], bfr[1][3]);
            }
            if (ks < 3) {
                ldsm4(bfr[1], bStage + 16 * ROWB + (ks + 1) * 32);
#pragma unroll
                for (int i = 0; i < 4; i++)
                    ldsm4(a[i], aStage + i * (16 * ROWB) + (ks + 1) * 32);
            }
        }
        if (pf) asm volatile("cp.async.commit_group;");
        st++; if (st >= NST) st = 0;
    }

    // -------- epilogue --------
    const long cr0 = m0 + wm * 64 + rg;
    const long cn0 = n0 + wn * 32 + 2 * lg;
#pragma unroll
    for (int i = 0; i < 4; i++) {
        const long r0 = cr0 + i * 16, r1 = r0 + 8;
#pragma unroll
        for (int j = 0; j < 4; j++) {
            const long cc = cn0 + j * 8;
            float v0 = acc[i][j][0], v1 = acc[i][j][1];
            float v2 = acc[i][j][2], v3 = acc[i][j][3];
            if (MODE == 0 || MODE == 3) {
                const float s0 = p0[cc], s1 = p0[cc + 1];
                const float h0 = p1[cc], h1 = p1[cc + 1];
                v0 = fmaf(v0, s0, h0); v1 = fmaf(v1, s1, h1);
                v2 = fmaf(v2, s0, h0); v3 = fmaf(v3, s1, h1);
            } else if (MODE == 1) {
                const __half* bias = pbh + (long)zi * bias_is;
                const float2 b0 = __half22float2(*(const __half2*)(bias + r0 * ldbias + cc));
                const float2 b1 = __half22float2(*(const __half2*)(bias + r1 * ldbias + cc));
                v0 = fmaf(v0, alpha, b0.x); v1 = fmaf(v1, alpha, b0.y);
                v2 = fmaf(v2, alpha, b1.x); v3 = fmaf(v3, alpha, b1.y);
            } else {
                v0 = fminf(fmaxf(v0, -1.f), 1.f);
                v1 = fminf(fmaxf(v1, -1.f), 1.f);
                v2 = fminf(fmaxf(v2, -1.f), 1.f);
                v3 = fminf(fmaxf(v3, -1.f), 1.f);
            }
            if (MODE != 3) {
                __half* Ch = (__half*)Call + (long)zo * cosz + (long)zi * cis;
                *(__half2*)(Ch + r0 * ldc + cc) = __floats2half2_rn(v0, v1);
                *(__half2*)(Ch + r1 * ldc + cc) = __floats2half2_rn(v2, v3);
            } else {
                float* Cf = (float*)Call + (long)zo * cosz + (long)zi * cis;
                *(float2*)(Cf + r0 * ldc + cc) = make_float2(v0, v1);
                *(float2*)(Cf + r1 * ldc + cc) = make_float2(v2, v3);
            }
        }
    }
}

// ---------------- small kernels ----------------
__global__ void bn_prep_kernel(const float* __restrict__ g, const float* __restrict__ b,
                               const float* __restrict__ mu, const float* __restrict__ var,
                               float* __restrict__ sc, float* __restrict__ sh, int n) {
    int i = blockIdx.x * blockDim.x + threadIdx.x;
    if (i < n) {
        float s = g[i] * rsqrtf(var[i] + EPS_);
        sc[i] = s;
        sh[i] = b[i] - mu[i] * s;
    }
}

__global__ void f2h_kernel(const float* __restrict__ in, __half* __restrict__ out, long n) {
    long i = ((long)blockIdx.x * blockDim.x + threadIdx.x) * 8;
    if (i < n) {
        float4 v0 = *(const float4*)(in + i);
        float4 v1 = *(const float4*)(in + i + 4);
        __half2* o = (__half2*)(out + i);
        o[0] = __floats2half2_rn(v0.x, v0.y);
        o[1] = __floats2half2_rn(v0.z, v0.w);
        o[2] = __floats2half2_rn(v1.x, v1.y);
        o[3] = __floats2half2_rn(v1.z, v1.w);
    }
}

// V transpose: qkvh[b,n][h*1024+512+d] -> vth[(b*8+h)*512+d][n]
__global__ void transpose_v_kernel(const __half* __restrict__ qkv, __half* __restrict__ vt) {
    __shared__ __half t[32][33];
    const int z = blockIdx.z, b = z >> 3, h = z & 7;
    const long n0 = (long)blockIdx.x * 32, d0 = (long)blockIdx.y * 32;
    const int tx = threadIdx.x, ty = threadIdx.y;
    const __half* src = qkv + (long)b * N_ * QKVC + (long)h * 1024 + 512;
#pragma unroll
    for (int i = 0; i < 32; i += 8)
        t[ty + i][tx] = src[(n0 + ty + i) * QKVC + d0 + tx];
    __syncthreads();
    __half* dst = vt + ((long)z * VD_ + d0) * N_ + n0;
#pragma unroll
    for (int i = 0; i < 32; i += 8)
        dst[(ty + i) * (long)N_ + tx] = t[tx][ty + i];
}

// rowwise softmax over 1024 half logits -> half probs (128 thr x 8 halves)
__global__ void softmax1024_kernel(const __half* __restrict__ attnl, __half* __restrict__ attnh) {
    const uint4* p = (const uint4*)(attnl + (long)blockIdx.x * 1024);
    uint4* ph = (uint4*)(attnh + (long)blockIdx.x * 1024);
    const int t = threadIdx.x;

    float2 f[4];
    {
        const uint4 u = p[t];
        f[0] = __half22float2(*(const __half2*)&u.x);
        f[1] = __half22float2(*(const __half2*)&u.y);
        f[2] = __half22float2(*(const __half2*)&u.z);
        f[3] = __half22float2(*(const __half2*)&u.w);
    }

    float m = -1e30f;
#pragma unroll
    for (int q = 0; q < 4; q++) m = fmaxf(m, fmaxf(f[q].x, f[q].y));
#pragma unroll
    for (int o = 16; o > 0; o >>= 1) m = fmaxf(m, __shfl_xor_sync(0xffffffffu, m, o));
    __shared__ float sm_[4], ss[4];
    if ((t & 31) == 0) sm_[t >> 5] = m;
    __syncthreads();
    m = fmaxf(fmaxf(sm_[0], sm_[1]), fmaxf(sm_[2], sm_[3]));

    float s = 0.f;
#pragma unroll
    for (int q = 0; q < 4; q++) {
        f[q].x = __expf(f[q].x - m); f[q].y = __expf(f[q].y - m);
        s += f[q].x + f[q].y;
    }
#pragma unroll
    for (int o = 16; o > 0; o >>= 1) s += __shfl_xor_sync(0xffffffffu, s, o);
    if ((t & 31) == 0) ss[t >> 5] = s;
    __syncthreads();
    s = ss[0] + ss[1] + ss[2] + ss[3];
    const float inv = 1.0f / s;

    uint4 o0;
    *(__half2*)&o0.x = __floats2half2_rn(f[0].x * inv, f[0].y * inv);
    *(__half2*)&o0.y = __floats2half2_rn(f[1].x * inv, f[1].y * inv);
    *(__half2*)&o0.z = __floats2half2_rn(f[2].x * inv, f[2].y * inv);
    *(__half2*)&o0.w = __floats2half2_rn(f[3].x * inv, f[3].y * inv);
    ph[t] = o0;
}

// ---------------- launch ----------------
extern "C" void kernel_launch(void* const* d_in, const int* in_sizes, int n_in,
                              void* d_out, int out_size) {
    const float* x          = (const float*)d_in[0];
    const float* qkv_w      = (const float*)d_in[1];
    const float* qkv_gamma  = (const float*)d_in[2];
    const float* qkv_beta   = (const float*)d_in[3];
    const float* qkv_mean   = (const float*)d_in[4];
    const float* qkv_var    = (const float*)d_in[5];
    const float* pos_bias   = (const float*)d_in[6];
    const float* proj_w     = (const float*)d_in[7];
    const float* proj_gamma = (const float*)d_in[8];
    const float* proj_beta  = (const float*)d_in[9];
    const float* proj_mean  = (const float*)d_in[10];
    const float* proj_var   = (const float*)d_in[11];
    float* out = (float*)d_out;

    __half *qkvh, *attnl, *attnh, *aoh, *vth, *xh, *wh, *pwh, *pbh;
    float *qs, *qh, *ps, *ph;
    cudaGetSymbolAddress((void**)&qkvh,  g_qkvh);
    cudaGetSymbolAddress((void**)&attnl, g_attnl);
    cudaGetSymbolAddress((void**)&attnh, g_attnh);
    cudaGetSymbolAddress((void**)&aoh,   g_aoh);
    cudaGetSymbolAddress((void**)&vth,   g_vth);
    cudaGetSymbolAddress((void**)&xh,    g_xh);
    cudaGetSymbolAddress((void**)&wh,    g_wh);
    cudaGetSymbolAddress((void**)&pwh,   g_pwh);
    cudaGetSymbolAddress((void**)&pbh,   g_pbh);
    cudaGetSymbolAddress((void**)&qs,    g_qs);
    cudaGetSymbolAddress((void**)&qh,    g_qh);
    cudaGetSymbolAddress((void**)&ps,    g_ps);
    cudaGetSymbolAddress((void**)&ph,    g_ph);

    cudaFuncSetAttribute(hgemm_kernel<0>, cudaFuncAttributeMaxDynamicSharedMemorySize, SMEM_BYTES);
    cudaFuncSetAttribute(hgemm_kernel<1>, cudaFuncAttributeMaxDynamicSharedMemorySize, SMEM_BYTES);
    cudaFuncSetAttribute(hgemm_kernel<2>, cudaFuncAttributeMaxDynamicSharedMemorySize, SMEM_BYTES);
    cudaFuncSetAttribute(hgemm_kernel<3>, cudaFuncAttributeMaxDynamicSharedMemorySize, SMEM_BYTES);

    bn_prep_kernel<<<(int)((QKVC + 255) / 256), 256>>>(qkv_gamma, qkv_beta, qkv_mean, qkv_var, qs, qh, (int)QKVC);
    f2h_kernel<<<(int)((MTOK * CIN / 8 + 255) / 256), 256>>>(x, xh, MTOK * CIN);
    f2h_kernel<<<(int)((QKVC * CIN / 8 + 255) / 256), 256>>>(qkv_w, wh, QKVC * CIN);

    const long perB = (long)N_ * QKVC;
    const long NN   = (long)N_ * N_;

    // 1) qkvh = half(BN(x @ qkv_w^T))   [16384 x 8192], K=768
    hgemm_kernel<0><<<dim3(QKVC / 128, MTOK / 128, 1), 256, SMEM_BYTES>>>(
        xh, CIN, 0, 0,
        wh, CIN, 0, 0,
        qkvh, QKVC, 0, 0,
        CIN, 1, qs, qh, nullptr, 0.f, 0, 0);

    f2h_kernel<<<(int)(((long)DOUT * NHV / 8 + 255) / 256), 256>>>(proj_w, pwh, (long)DOUT * NHV);
    f2h_kernel<<<(int)(((long)H_ * NN / 8 + 255) / 256), 256>>>(pos_bias, pbh, (long)H_ * NN);
    bn_prep_kernel<<<(DOUT + 255) / 256, 256>>>(proj_gamma, proj_beta, proj_mean, proj_var, ps, ph, DOUT);

    // 1b) V transpose (half)
    transpose_v_kernel<<<dim3(N_ / 32, VD_ / 32, B_ * H_), dim3(32, 8)>>>(qkvh, vth);

    // 2) half logits = q @ k^T * SCALE + pos_bias[h]   per (b,h): [1024 x 1024], K=256
    hgemm_kernel<1><<<dim3(N_ / 128, N_ / 128, B_ * H_), 256, SMEM_BYTES>>>(
        qkvh,       QKVC, perB, 1024,
        qkvh + 256, QKVC, perB, 1024,
        attnl, N_, 8 * NN, NN,
        KQ_, H_, nullptr, nullptr, pbh, SCALE_, NN, N_);

    // 3) softmax (half in, half out)
    softmax1024_kernel<<<(unsigned)(B_ * H_ * N_), 128>>>(attnl, attnh);

    // 4) aoh = half(clip(attnh @ vth^T)) per (b,h): [1024 x 512], K=1024
    hgemm_kernel<2><<<dim3(VD_ / 128, N_ / 128, B_ * H_), 256, SMEM_BYTES>>>(
        attnh, N_, 8 * NN, NN,
        vth, N_, 8L * VD_ * N_, (long)VD_ * N_,
        aoh, NHV, (long)N_ * NHV, VD_,
        N_, H_, nullptr, nullptr, nullptr, 0.f, 0, 0);

    // 5) out = BN(aoh @ proj_w^T)   [16384 x 512], K=4096
    hgemm_kernel<3><<<dim3(DOUT / 128, MTOK / 128, 1), 256, SMEM_BYTES>>>(
        aoh, NHV, 0, 0,
        pwh, NHV, 0, 0,
        out, DOUT, 0, 0,
        (int)NHV, 1, ps, ph, nullptr, 0.f, 0, 0);
}

// round 13
// speedup vs baseline: 1.5112x; 1.5112x over previous
#include <cuda_runtime.h>
#include <cuda_fp16.h>
#include <cstdint>

// ---------------- problem constants ----------------
constexpr int  B_    = 16;
constexpr int  N_    = 1024;
constexpr int  CIN   = 768;
constexpr int  H_    = 8;
constexpr int  KQ_   = 256;
constexpr int  VD_   = 512;
constexpr long MTOK  = 16384;
constexpr long QKVC  = 8192;
constexpr long NHV   = 4096;
constexpr int  DOUT  = 512;
constexpr float SCALE_ = 0.04419417382415922f;     // 512^-0.5
constexpr float EPS_   = 1e-5f;

// ---------------- scratch (device globals) ----------------
__device__ __half g_qkvh [MTOK * QKVC];
__device__ __half g_attnl[(long)B_ * H_ * N_ * N_];   // half logits
__device__ __half g_attnh[(long)B_ * H_ * N_ * N_];   // half probs
__device__ __half g_aoh  [MTOK * NHV];
__device__ __half g_vth  [(long)B_ * H_ * VD_ * N_];
__device__ __half g_xh   [MTOK * CIN];
__device__ __half g_wh   [QKVC * CIN];
__device__ __half g_pwh  [(long)DOUT * NHV];
__device__ __half g_pbh  [(long)H_ * N_ * N_];        // half pos_bias
__device__ float  g_qs[QKVC], g_qh[QKVC];
__device__ float  g_ps[DOUT], g_ph[DOUT];

// ---------------- helpers ----------------
__device__ __forceinline__ void cp16(uint32_t s, const void* g) {
    asm volatile("cp.async.cg.shared.global [%0], [%1], 16;"
                 :: "r"(s), "l"(__cvta_generic_to_global(g)));
}
__device__ __forceinline__ uint32_t smem_u32(const void* p) {
    uint32_t a;
    asm("{ .reg .u64 t; cvta.to.shared.u64 t, %1; cvt.u32.u64 %0, t; }" : "=r"(a) : "l"(p));
    return a;
}
__device__ __forceinline__ void mma_f16(float* c, const uint32_t* a, uint32_t b0, uint32_t b1) {
    asm volatile(
        "mma.sync.aligned.m16n8k16.row.col.f32.f16.f16.f32 "
        "{%0,%1,%2,%3}, {%4,%5,%6,%7}, {%8,%9}, {%0,%1,%2,%3};"
        : "+f"(c[0]), "+f"(c[1]), "+f"(c[2]), "+f"(c[3])
        : "r"(a[0]), "r"(a[1]), "r"(a[2]), "r"(a[3]), "r"(b0), "r"(b1));
}
__device__ __forceinline__ void ldsm4(uint32_t* r, uint32_t a) {
    asm volatile("ldmatrix.sync.aligned.m8n8.x4.shared.b16 {%0,%1,%2,%3}, [%4];"
                 : "=r"(r[0]), "=r"(r[1]), "=r"(r[2]), "=r"(r[3]) : "r"(a));
}

// ---------------- fp16 mma GEMM: tile 128x128, K-chunk 64, 3-stage, occ 2 -------------
// A: [M][K] K-contig half. B: [N][K] K-contig half (C = A * B^T).
// MODE 0: half(BN)  1: half(alpha*acc + half bias)  2: half(clamp(-1,1))  3: fp32 BN
constexpr int LDT   = 36;
constexpr int ROWB  = LDT * 4;              // 144 bytes per row
constexpr int CH    = 128 * LDT;
constexpr int CHB   = CH * 4;               // 18432 bytes per tile buffer
constexpr int NST   = 3;
constexpr int SMEM_BYTES = 2 * NST * CHB;   // 110592 B -> 2 CTAs/SM

template<int MODE>
__global__ __launch_bounds__(256, 2)
void hgemm_kernel(const __half* __restrict__ Aall, long lda, long aos, long ais,
                  const __half* __restrict__ Ball, long ldb, long bos, long bis,
                  void* __restrict__ Call, long ldc, long cosz, long cis,
                  int K, int zdiv,
                  const float* __restrict__ p0, const float* __restrict__ p1,
                  const __half* __restrict__ pbh,
                  float alpha, long bias_is, long ldbias)
{
    extern __shared__ uint32_t smw[];
    const uint32_t sbase = smem_u32(smw);

    const int tid = threadIdx.x;
    const int wid = tid >> 5, lane = tid & 31;
    const int wm = wid & 1, wn = wid >> 1;
    const int rg = lane >> 2, lg = lane & 3;

    const int z  = blockIdx.z;
    const int zo = z / zdiv, zi = z - zo * zdiv;
    const __half* A  = Aall + (long)zo * aos + (long)zi * ais;
    const __half* Bp = Ball + (long)zo * bos + (long)zi * bis;
    const long m0 = (long)blockIdx.y * 128;
    const long n0 = (long)blockIdx.x * 128;

    float acc[4][4][4];
#pragma unroll
    for (int i = 0; i < 4; i++)
#pragma unroll
        for (int j = 0; j < 4; j++)
#pragma unroll
            for (int q = 0; q < 4; q++) acc[i][j][q] = 0.f;

    auto load_tile = [&](const __half* src, long ld, int kc, uint32_t bufByteOff) {
        const __half* s = src + (long)kc * 64;
#pragma unroll
        for (int i = 0; i < 4; i++) {
            int idx = tid + i * 256;
            int r = idx >> 3, c = idx & 7;
            cp16(sbase + bufByteOff + (uint32_t)(r * ROWB + c * 16),
                 s + (long)r * ld + c * 8);
        }
    };

    const __half* Abase = A + m0 * lda;
    const __half* Bbase = Bp + n0 * ldb;

    const uint32_t aOff = (uint32_t)((wm * 64 + (lane & 15)) * ROWB + ((lane >> 4) & 1) * 16);
    const uint32_t bOff = (uint32_t)((wn * 32 + ((lane >> 4) & 1) * 8 + (lane & 7)) * ROWB
                                     + ((lane >> 3) & 1) * 16);

    const int nch = K >> 6;
    load_tile(Abase, lda, 0, 0);
    load_tile(Bbase, ldb, 0, NST * CHB);
    asm volatile("cp.async.commit_group;");
    load_tile(Abase, lda, 1, CHB);
    load_tile(Bbase, ldb, 1, NST * CHB + CHB);
    asm volatile("cp.async.commit_group;");

    int st = 0;
    for (int kc = 0; kc < nch; kc++) {
        if (kc + 1 < nch) asm volatile("cp.async.wait_group 1;");
        else              asm volatile("cp.async.wait_group 0;");
        __syncthreads();

        const bool pf = (kc + 2 < nch);
        int s2 = st + 2; if (s2 >= NST) s2 -= NST;
        const uint32_t aPB = sbase + (uint32_t)(s2 * CHB);
        const uint32_t bPB = sbase + (uint32_t)(NST * CHB + s2 * CHB);
        const __half* aPS = Abase + (long)(kc + 2) * 64;
        const __half* bPS = Bbase + (long)(kc + 2) * 64;

        const uint32_t aStage = sbase + st * CHB + aOff;
        const uint32_t bStage = sbase + NST * CHB + st * CHB + bOff;

        // fragments for ks = 0
        uint32_t a[4][4], bfr[2][4];
#pragma unroll
        for (int i = 0; i < 4; i++) ldsm4(a[i], aStage + i * (16 * ROWB));
        ldsm4(bfr[0], bStage);
        ldsm4(bfr[1], bStage + 16 * ROWB);

#pragma unroll
        for (int ks = 0; ks < 4; ks++) {
            // spread gmem->smem prefetch (2 cp.async per ks)
            if (pf) {
                int idx = tid + ks * 256;
                int r = idx >> 3, c = idx & 7;
                cp16(aPB + (uint32_t)(r * ROWB + c * 16), aPS + (long)r * lda + c * 8);
                cp16(bPB + (uint32_t)(r * ROWB + c * 16), bPS + (long)r * ldb + c * 8);
            }
            // j-pair 0 consumes bfr[0]
#pragma unroll
            for (int i = 0; i < 4; i++) {
                mma_f16(acc[i][0], a[i], bfr[0][0], bfr[0][1]);
                mma_f16(acc[i][1], a[i], bfr[0][2], bfr[0][3]);
            }
            if (ks < 3) ldsm4(bfr[0], bStage + (ks + 1) * 32);               // rotate in place
            // j-pair 1 consumes bfr[1]
#pragma unroll
            for (int i = 0; i < 4; i++) {
                mma_f16(acc[i][2], a[i], bfr[1][0], bfr[1][1]);
                mma_f16(acc[i][3], a[i], bfr[1][2], bfr[1][3]);
            }
            if (ks < 3) {
                ldsm4(bfr[1], bStage + 16 * ROWB + (ks + 1) * 32);
#pragma unroll
                for (int i = 0; i < 4; i++)
                    ldsm4(a[i], aStage + i * (16 * ROWB) + (ks + 1) * 32);
            }
        }
        if (pf) asm volatile("cp.async.commit_group;");
        st++; if (st >= NST) st = 0;
    }

    // -------- epilogue --------
    const long cr0 = m0 + wm * 64 + rg;
    const long cn0 = n0 + wn * 32 + 2 * lg;
#pragma unroll
    for (int i = 0; i < 4; i++) {
        const long r0 = cr0 + i * 16, r1 = r0 + 8;
#pragma unroll
        for (int j = 0; j < 4; j++) {
            const long cc = cn0 + j * 8;
            float v0 = acc[i][j][0], v1 = acc[i][j][1];
            float v2 = acc[i][j][2], v3 = acc[i][j][3];
            if (MODE == 0 || MODE == 3) {
                const float s0 = p0[cc], s1 = p0[cc + 1];
                const float h0 = p1[cc], h1 = p1[cc + 1];
                v0 = fmaf(v0, s0, h0); v1 = fmaf(v1, s1, h1);
                v2 = fmaf(v2, s0, h0); v3 = fmaf(v3, s1, h1);
            } else if (MODE == 1) {
                const __half* bias = pbh + (long)zi * bias_is;
                const float2 b0 = __half22float2(*(const __half2*)(bias + r0 * ldbias + cc));
                const float2 b1 = __half22float2(*(const __half2*)(bias + r1 * ldbias + cc));
                v0 = fmaf(v0, alpha, b0.x); v1 = fmaf(v1, alpha, b0.y);
                v2 = fmaf(v2, alpha, b1.x); v3 = fmaf(v3, alpha, b1.y);
            } else {
                v0 = fminf(fmaxf(v0, -1.f), 1.f);
                v1 = fminf(fmaxf(v1, -1.f), 1.f);
                v2 = fminf(fmaxf(v2, -1.f), 1.f);
                v3 = fminf(fmaxf(v3, -1.f), 1.f);
            }
            if (MODE != 3) {
                __half* Ch = (__half*)Call + (long)zo * cosz + (long)zi * cis;
                *(__half2*)(Ch + r0 * ldc + cc) = __floats2half2_rn(v0, v1);
                *(__half2*)(Ch + r1 * ldc + cc) = __floats2half2_rn(v2, v3);
            } else {
                float* Cf = (float*)Call + (long)zo * cosz + (long)zi * cis;
                *(float2*)(Cf + r0 * ldc + cc) = make_float2(v0, v1);
                *(float2*)(Cf + r1 * ldc + cc) = make_float2(v2, v3);
            }
        }
    }
}

// ---------------- small kernels ----------------
__global__ void bn_prep_kernel(const float* __restrict__ g, const float* __restrict__ b,
                               const float* __restrict__ mu, const float* __restrict__ var,
                               float* __restrict__ sc, float* __restrict__ sh, int n) {
    int i = blockIdx.x * blockDim.x + threadIdx.x;
    if (i < n) {
        float s = g[i] * rsqrtf(var[i] + EPS_);
        sc[i] = s;
        sh[i] = b[i] - mu[i] * s;
    }
}

__global__ void f2h_kernel(const float* __restrict__ in, __half* __restrict__ out, long n) {
    long i = ((long)blockIdx.x * blockDim.x + threadIdx.x) * 8;
    if (i < n) {
        float4 v0 = *(const float4*)(in + i);
        float4 v1 = *(const float4*)(in + i + 4);
        __half2* o = (__half2*)(out + i);
        o[0] = __floats2half2_rn(v0.x, v0.y);
        o[1] = __floats2half2_rn(v0.z, v0.w);
        o[2] = __floats2half2_rn(v1.x, v1.y);
        o[3] = __floats2half2_rn(v1.z, v1.w);
    }
}

// V transpose: qkvh[b,n][h*1024+512+d] -> vth[(b*8+h)*512+d][n]
__global__ void transpose_v_kernel(const __half* __restrict__ qkv, __half* __restrict__ vt) {
    __shared__ __half t[32][33];
    const int z = blockIdx.z, b = z >> 3, h = z & 7;
    const long n0 = (long)blockIdx.x * 32, d0 = (long)blockIdx.y * 32;
    const int tx = threadIdx.x, ty = threadIdx.y;
    const __half* src = qkv + (long)b * N_ * QKVC + (long)h * 1024 + 512;
#pragma unroll
    for (int i = 0; i < 32; i += 8)
        t[ty + i][tx] = src[(n0 + ty + i) * QKVC + d0 + tx];
    __syncthreads();
    __half* dst = vt + ((long)z * VD_ + d0) * N_ + n0;
#pragma unroll
    for (int i = 0; i < 32; i += 8)
        dst[(ty + i) * (long)N_ + tx] = t[tx][ty + i];
}

// rowwise softmax over 1024 half logits -> half probs (128 thr x 8 halves)
__global__ void softmax1024_kernel(const __half* __restrict__ attnl, __half* __restrict__ attnh) {
    const uint4* p = (const uint4*)(attnl + (long)blockIdx.x * 1024);
    uint4* ph = (uint4*)(attnh + (long)blockIdx.x * 1024);
    const int t = threadIdx.x;

    float2 f[4];
    {
        const uint4 u = p[t];
        f[0] = __half22float2(*(const __half2*)&u.x);
        f[1] = __half22float2(*(const __half2*)&u.y);
        f[2] = __half22float2(*(const __half2*)&u.z);
        f[3] = __half22float2(*(const __half2*)&u.w);
    }

    float m = -1e30f;
#pragma unroll
    for (int q = 0; q < 4; q++) m = fmaxf(m, fmaxf(f[q].x, f[q].y));
#pragma unroll
    for (int o = 16; o > 0; o >>= 1) m = fmaxf(m, __shfl_xor_sync(0xffffffffu, m, o));
    __shared__ float sm_[4], ss[4];
    if ((t & 31) == 0) sm_[t >> 5] = m;
    __syncthreads();
    m = fmaxf(fmaxf(sm_[0], sm_[1]), fmaxf(sm_[2], sm_[3]));

    float s = 0.f;
#pragma unroll
    for (int q = 0; q < 4; q++) {
        f[q].x = __expf(f[q].x - m); f[q].y = __expf(f[q].y - m);
        s += f[q].x + f[q].y;
    }
#pragma unroll
    for (int o = 16; o > 0; o >>= 1) s += __shfl_xor_sync(0xffffffffu, s, o);
    if ((t & 31) == 0) ss[t >> 5] = s;
    __syncthreads();
    s = ss[0] + ss[1] + ss[2] + ss[3];
    const float inv = 1.0f / s;

    uint4 o0;
    *(__half2*)&o0.x = __floats2half2_rn(f[0].x * inv, f[0].y * inv);
    *(__half2*)&o0.y = __floats2half2_rn(f[1].x * inv, f[1].y * inv);
    *(__half2*)&o0.z = __floats2half2_rn(f[2].x * inv, f[2].y * inv);
    *(__half2*)&o0.w = __floats2half2_rn(f[3].x * inv, f[3].y * inv);
    ph[t] = o0;
}

// ---------------- launch ----------------
extern "C" void kernel_launch(void* const* d_in, const int* in_sizes, int n_in,
                              void* d_out, int out_size) {
    const float* x          = (const float*)d_in[0];
    const float* qkv_w      = (const float*)d_in[1];
    const float* qkv_gamma  = (const float*)d_in[2];
    const float* qkv_beta   = (const float*)d_in[3];
    const float* qkv_mean   = (const float*)d_in[4];
    const float* qkv_var    = (const float*)d_in[5];
    const float* pos_bias   = (const float*)d_in[6];
    const float* proj_w     = (const float*)d_in[7];
    const float* proj_gamma = (const float*)d_in[8];
    const float* proj_beta  = (const float*)d_in[9];
    const float* proj_mean  = (const float*)d_in[10];
    const float* proj_var   = (const float*)d_in[11];
    float* out = (float*)d_out;

    __half *qkvh, *attnl, *attnh, *aoh, *vth, *xh, *wh, *pwh, *pbh;
    float *qs, *qh, *ps, *ph;
    cudaGetSymbolAddress((void**)&qkvh,  g_qkvh);
    cudaGetSymbolAddress((void**)&attnl, g_attnl);
    cudaGetSymbolAddress((void**)&attnh, g_attnh);
    cudaGetSymbolAddress((void**)&aoh,   g_aoh);
    cudaGetSymbolAddress((void**)&vth,   g_vth);
    cudaGetSymbolAddress((void**)&xh,    g_xh);
    cudaGetSymbolAddress((void**)&wh,    g_wh);
    cudaGetSymbolAddress((void**)&pwh,   g_pwh);
    cudaGetSymbolAddress((void**)&pbh,   g_pbh);
    cudaGetSymbolAddress((void**)&qs,    g_qs);
    cudaGetSymbolAddress((void**)&qh,    g_qh);
    cudaGetSymbolAddress((void**)&ps,    g_ps);
    cudaGetSymbolAddress((void**)&ph,    g_ph);

    cudaFuncSetAttribute(hgemm_kernel<0>, cudaFuncAttributeMaxDynamicSharedMemorySize, SMEM_BYTES);
    cudaFuncSetAttribute(hgemm_kernel<1>, cudaFuncAttributeMaxDynamicSharedMemorySize, SMEM_BYTES);
    cudaFuncSetAttribute(hgemm_kernel<2>, cudaFuncAttributeMaxDynamicSharedMemorySize, SMEM_BYTES);
    cudaFuncSetAttribute(hgemm_kernel<3>, cudaFuncAttributeMaxDynamicSharedMemorySize, SMEM_BYTES);

    bn_prep_kernel<<<(int)((QKVC + 255) / 256), 256>>>(qkv_gamma, qkv_beta, qkv_mean, qkv_var, qs, qh, (int)QKVC);
    f2h_kernel<<<(int)((MTOK * CIN / 8 + 255) / 256), 256>>>(x, xh, MTOK * CIN);
    f2h_kernel<<<(int)((QKVC * CIN / 8 + 255) / 256), 256>>>(qkv_w, wh, QKVC * CIN);

    const long perB = (long)N_ * QKVC;
    const long NN   = (long)N_ * N_;

    // 1) qkvh = half(BN(x @ qkv_w^T))   [16384 x 8192], K=768
    hgemm_kernel<0><<<dim3(QKVC / 128, MTOK / 128, 1), 256, SMEM_BYTES>>>(
        xh, CIN, 0, 0,
        wh, CIN, 0, 0,
        qkvh, QKVC, 0, 0,
        CIN, 1, qs, qh, nullptr, 0.f, 0, 0);

    f2h_kernel<<<(int)(((long)DOUT * NHV / 8 + 255) / 256), 256>>>(proj_w, pwh, (long)DOUT * NHV);
    f2h_kernel<<<(int)(((long)H_ * NN / 8 + 255) / 256), 256>>>(pos_bias, pbh, (long)H_ * NN);
    bn_prep_kernel<<<(DOUT + 255) / 256, 256>>>(proj_gamma, proj_beta, proj_mean, proj_var, ps, ph, DOUT);

    // 1b) V transpose (half)
    transpose_v_kernel<<<dim3(N_ / 32, VD_ / 32, B_ * H_), dim3(32, 8)>>>(qkvh, vth);

    // 2) half logits = q @ k^T * SCALE + pos_bias[h]   per (b,h): [1024 x 1024], K=256
    hgemm_kernel<1><<<dim3(N_ / 128, N_ / 128, B_ * H_), 256, SMEM_BYTES>>>(
        qkvh,       QKVC, perB, 1024,
        qkvh + 256, QKVC, perB, 1024,
        attnl, N_, 8 * NN, NN,
        KQ_, H_, nullptr, nullptr, pbh, SCALE_, NN, N_);

    // 3) softmax (half in, half out)
    softmax1024_kernel<<<(unsigned)(B_ * H_ * N_), 128>>>(attnl, attnh);

    // 4) aoh = half(clip(attnh @ vth^T)) per (b,h): [1024 x 512], K=1024
    hgemm_kernel<2><<<dim3(VD_ / 128, N_ / 128, B_ * H_), 256, SMEM_BYTES>>>(
        attnh, N_, 8 * NN, NN,
        vth, N_, 8L * VD_ * N_, (long)VD_ * N_,
        aoh, NHV, (long)N_ * NHV, VD_,
        N_, H_, nullptr, nullptr, nullptr, 0.f, 0, 0);

    // 5) out = BN(aoh @ proj_w^T)   [16384 x 512], K=4096
    hgemm_kernel<3><<<dim3(DOUT / 128, MTOK / 128, 1), 256, SMEM_BYTES>>>(
        aoh, NHV, 0, 0,
        pwh, NHV, 0, 0,
        out, DOUT, 0, 0,
        (int)NHV, 1, ps, ph, nullptr, 0.f, 0, 0);
}

// round 14
// speedup vs baseline: 1.5165x; 1.0035x over previous
#include <cuda_runtime.h>
#include <cuda_fp16.h>
#include <cstdint>

// ---------------- problem constants ----------------
constexpr int  B_    = 16;
constexpr int  N_    = 1024;
constexpr int  CIN   = 768;
constexpr int  H_    = 8;
constexpr int  KQ_   = 256;
constexpr int  VD_   = 512;
constexpr long MTOK  = 16384;
constexpr long QKVC  = 8192;
constexpr long NHV   = 4096;
constexpr int  DOUT  = 512;
constexpr float SCALE_ = 0.04419417382415922f;     // 512^-0.5
constexpr float EPS_   = 1e-5f;

// ---------------- scratch (device globals) ----------------
__device__ __half g_qkvh [MTOK * QKVC];
__device__ __half g_attnl[(long)B_ * H_ * N_ * N_];   // half logits
__device__ __half g_attnh[(long)B_ * H_ * N_ * N_];   // half probs
__device__ __half g_aoh  [MTOK * NHV];
__device__ __half g_vth  [(long)B_ * H_ * VD_ * N_];
__device__ __half g_xh   [MTOK * CIN];
__device__ __half g_wh   [QKVC * CIN];
__device__ __half g_pwh  [(long)DOUT * NHV];
__device__ __half g_pbh  [(long)H_ * N_ * N_];        // half pos_bias
__device__ float  g_qs[QKVC], g_qh[QKVC];
__device__ float  g_ps[DOUT], g_ph[DOUT];

// ---------------- helpers ----------------
__device__ __forceinline__ void cp16(uint32_t s, const void* g) {
    asm volatile("cp.async.cg.shared.global [%0], [%1], 16;"
                 :: "r"(s), "l"(__cvta_generic_to_global(g)));
}
__device__ __forceinline__ uint32_t smem_u32(const void* p) {
    uint32_t a;
    asm("{ .reg .u64 t; cvta.to.shared.u64 t, %1; cvt.u32.u64 %0, t; }" : "=r"(a) : "l"(p));
    return a;
}
__device__ __forceinline__ void mma_f16(float* c, const uint32_t* a, uint32_t b0, uint32_t b1) {
    asm volatile(
        "mma.sync.aligned.m16n8k16.row.col.f32.f16.f16.f32 "
        "{%0,%1,%2,%3}, {%4,%5,%6,%7}, {%8,%9}, {%0,%1,%2,%3};"
        : "+f"(c[0]), "+f"(c[1]), "+f"(c[2]), "+f"(c[3])
        : "r"(a[0]), "r"(a[1]), "r"(a[2]), "r"(a[3]), "r"(b0), "r"(b1));
}
__device__ __forceinline__ void ldsm4(uint32_t* r, uint32_t a) {
    asm volatile("ldmatrix.sync.aligned.m8n8.x4.shared.b16 {%0,%1,%2,%3}, [%4];"
                 : "=r"(r[0]), "=r"(r[1]), "=r"(r[2]), "=r"(r[3]) : "r"(a));
}

// ---------------- fp16 mma GEMM: tile 128x128, K-chunk 64, 3-stage, occ 2 -------------
// A: [M][K] K-contig half. B: [N][K] K-contig half (C = A * B^T).
// MODE 0: half(BN)  1: half(alpha*acc + half bias)  2: half(clamp(-1,1))  3: fp32 BN
constexpr int LDT   = 36;
constexpr int ROWB  = LDT * 4;              // 144 bytes per row
constexpr int CH    = 128 * LDT;
constexpr int CHB   = CH * 4;               // 18432 bytes per tile buffer
constexpr int NST   = 3;
constexpr int SMEM_BYTES = 2 * NST * CHB;   // 110592 B -> 2 CTAs/SM

template<int MODE>
__global__ __launch_bounds__(256, 2)
void hgemm_kernel(const __half* __restrict__ Aall, long lda, long aos, long ais,
                  const __half* __restrict__ Ball, long ldb, long bos, long bis,
                  void* __restrict__ Call, long ldc, long cosz, long cis,
                  int K, int zdiv,
                  const float* __restrict__ p0, const float* __restrict__ p1,
                  const __half* __restrict__ pbh,
                  float alpha, long bias_is, long ldbias)
{
    extern __shared__ uint32_t smw[];
    const uint32_t sbase = smem_u32(smw);

    const int tid = threadIdx.x;
    const int wid = tid >> 5, lane = tid & 31;
    const int wm = wid & 1, wn = wid >> 1;
    const int rg = lane >> 2, lg = lane & 3;

    const int z  = blockIdx.z;
    const int zo = z / zdiv, zi = z - zo * zdiv;
    const __half* A  = Aall + (long)zo * aos + (long)zi * ais;
    const __half* Bp = Ball + (long)zo * bos + (long)zi * bis;
    const long m0 = (long)blockIdx.y * 128;
    const long n0 = (long)blockIdx.x * 128;

    float acc[4][4][4];
#pragma unroll
    for (int i = 0; i < 4; i++)
#pragma unroll
        for (int j = 0; j < 4; j++)
#pragma unroll
            for (int q = 0; q < 4; q++) acc[i][j][q] = 0.f;

    auto load_tile = [&](const __half* src, long ld, int kc, uint32_t bufByteOff) {
        const __half* s = src + (long)kc * 64;
#pragma unroll
        for (int i = 0; i < 4; i++) {
            int idx = tid + i * 256;
            int r = idx >> 3, c = idx & 7;
            cp16(sbase + bufByteOff + (uint32_t)(r * ROWB + c * 16),
                 s + (long)r * ld + c * 8);
        }
    };

    const __half* Abase = A + m0 * lda;
    const __half* Bbase = Bp + n0 * ldb;

    const uint32_t aOff = (uint32_t)((wm * 64 + (lane & 15)) * ROWB + ((lane >> 4) & 1) * 16);
    const uint32_t bOff = (uint32_t)((wn * 32 + ((lane >> 4) & 1) * 8 + (lane & 7)) * ROWB
                                     + ((lane >> 3) & 1) * 16);

    const int nch = K >> 6;
    load_tile(Abase, lda, 0, 0);
    load_tile(Bbase, ldb, 0, NST * CHB);
    asm volatile("cp.async.commit_group;");
    load_tile(Abase, lda, 1, CHB);
    load_tile(Bbase, ldb, 1, NST * CHB + CHB);
    asm volatile("cp.async.commit_group;");

    int st = 0;
    for (int kc = 0; kc < nch; kc++) {
        if (kc + 1 < nch) asm volatile("cp.async.wait_group 1;");
        else              asm volatile("cp.async.wait_group 0;");
        __syncthreads();

        const bool pf = (kc + 2 < nch);
        int s2 = st + 2; if (s2 >= NST) s2 -= NST;
        const uint32_t aPB = sbase + (uint32_t)(s2 * CHB);
        const uint32_t bPB = sbase + (uint32_t)(NST * CHB + s2 * CHB);
        const __half* aPS = Abase + (long)(kc + 2) * 64;
        const __half* bPS = Bbase + (long)(kc + 2) * 64;

        const uint32_t aStage = sbase + st * CHB + aOff;
        const uint32_t bStage = sbase + NST * CHB + st * CHB + bOff;

        // fragments for ks = 0
        uint32_t a[4][4], bfr[2][4];
#pragma unroll
        for (int i = 0; i < 4; i++) ldsm4(a[i], aStage + i * (16 * ROWB));
        ldsm4(bfr[0], bStage);
        ldsm4(bfr[1], bStage + 16 * ROWB);

#pragma unroll
        for (int ks = 0; ks < 4; ks++) {
            // spread gmem->smem prefetch (2 cp.async per ks)
            if (pf) {
                int idx = tid + ks * 256;
                int r = idx >> 3, c = idx & 7;
                cp16(aPB + (uint32_t)(r * ROWB + c * 16), aPS + (long)r * lda + c * 8);
                cp16(bPB + (uint32_t)(r * ROWB + c * 16), bPS + (long)r * ldb + c * 8);
            }
            // j-pair 0 consumes bfr[0]
#pragma unroll
            for (int i = 0; i < 4; i++) {
                mma_f16(acc[i][0], a[i], bfr[0][0], bfr[0][1]);
                mma_f16(acc[i][1], a[i], bfr[0][2], bfr[0][3]);
            }
            if (ks < 3) ldsm4(bfr[0], bStage + (ks + 1) * 32);               // rotate in place
            // j-pair 1 consumes bfr[1]
#pragma unroll
            for (int i = 0; i < 4; i++) {
                mma_f16(acc[i][2], a[i], bfr[1][0], bfr[1][1]);
                mma_f16(acc[i][3], a[i], bfr[1][2], bfr[1][3]);
            }
            if (ks < 3) {
                ldsm4(bfr[1], bStage + 16 * ROWB + (ks + 1) * 32);
#pragma unroll
                for (int i = 0; i < 4; i++)
                    ldsm4(a[i], aStage + i * (16 * ROWB) + (ks + 1) * 32);
            }
        }
        if (pf) asm volatile("cp.async.commit_group;");
        st++; if (st >= NST) st = 0;
    }

    // -------- epilogue --------
    const long cr0 = m0 + wm * 64 + rg;
    const long cn0 = n0 + wn * 32 + 2 * lg;
#pragma unroll
    for (int i = 0; i < 4; i++) {
        const long r0 = cr0 + i * 16, r1 = r0 + 8;
#pragma unroll
        for (int j = 0; j < 4; j++) {
            const long cc = cn0 + j * 8;
            float v0 = acc[i][j][0], v1 = acc[i][j][1];
            float v2 = acc[i][j][2], v3 = acc[i][j][3];
            if (MODE == 0 || MODE == 3) {
                const float s0 = p0[cc], s1 = p0[cc + 1];
                const float h0 = p1[cc], h1 = p1[cc + 1];
                v0 = fmaf(v0, s0, h0); v1 = fmaf(v1, s1, h1);
                v2 = fmaf(v2, s0, h0); v3 = fmaf(v3, s1, h1);
            } else if (MODE == 1) {
                const __half* bias = pbh + (long)zi * bias_is;
                const float2 b0 = __half22float2(*(const __half2*)(bias + r0 * ldbias + cc));
                const float2 b1 = __half22float2(*(const __half2*)(bias + r1 * ldbias + cc));
                v0 = fmaf(v0, alpha, b0.x); v1 = fmaf(v1, alpha, b0.y);
                v2 = fmaf(v2, alpha, b1.x); v3 = fmaf(v3, alpha, b1.y);
            } else {
                v0 = fminf(fmaxf(v0, -1.f), 1.f);
                v1 = fminf(fmaxf(v1, -1.f), 1.f);
                v2 = fminf(fmaxf(v2, -1.f), 1.f);
                v3 = fminf(fmaxf(v3, -1.f), 1.f);
            }
            if (MODE != 3) {
                __half* Ch = (__half*)Call + (long)zo * cosz + (long)zi * cis;
                *(__half2*)(Ch + r0 * ldc + cc) = __floats2half2_rn(v0, v1);
                *(__half2*)(Ch + r1 * ldc + cc) = __floats2half2_rn(v2, v3);
            } else {
                float* Cf = (float*)Call + (long)zo * cosz + (long)zi * cis;
                *(float2*)(Cf + r0 * ldc + cc) = make_float2(v0, v1);
                *(float2*)(Cf + r1 * ldc + cc) = make_float2(v2, v3);
            }
        }
    }
}

// ---------------- small kernels ----------------
__global__ void bn_prep_kernel(const float* __restrict__ g, const float* __restrict__ b,
                               const float* __restrict__ mu, const float* __restrict__ var,
                               float* __restrict__ sc, float* __restrict__ sh, int n) {
    int i = blockIdx.x * blockDim.x + threadIdx.x;
    if (i < n) {
        float s = g[i] * rsqrtf(var[i] + EPS_);
        sc[i] = s;
        sh[i] = b[i] - mu[i] * s;
    }
}

__global__ void f2h_kernel(const float* __restrict__ in, __half* __restrict__ out, long n) {
    long i = ((long)blockIdx.x * blockDim.x + threadIdx.x) * 8;
    if (i < n) {
        float4 v0 = *(const float4*)(in + i);
        float4 v1 = *(const float4*)(in + i + 4);
        __half2* o = (__half2*)(out + i);
        o[0] = __floats2half2_rn(v0.x, v0.y);
        o[1] = __floats2half2_rn(v0.z, v0.w);
        o[2] = __floats2half2_rn(v1.x, v1.y);
        o[3] = __floats2half2_rn(v1.z, v1.w);
    }
}

// V transpose: qkvh[b,n][h*1024+512+d] -> vth[(b*8+h)*512+d][n]
__global__ void transpose_v_kernel(const __half* __restrict__ qkv, __half* __restrict__ vt) {
    __shared__ __half t[32][33];
    const int z = blockIdx.z, b = z >> 3, h = z & 7;
    const long n0 = (long)blockIdx.x * 32, d0 = (long)blockIdx.y * 32;
    const int tx = threadIdx.x, ty = threadIdx.y;
    const __half* src = qkv + (long)b * N_ * QKVC + (long)h * 1024 + 512;
#pragma unroll
    for (int i = 0; i < 32; i += 8)
        t[ty + i][tx] = src[(n0 + ty + i) * QKVC + d0 + tx];
    __syncthreads();
    __half* dst = vt + ((long)z * VD_ + d0) * N_ + n0;
#pragma unroll
    for (int i = 0; i < 32; i += 8)
        dst[(ty + i) * (long)N_ + tx] = t[tx][ty + i];
}

// rowwise softmax over 1024 half logits -> half probs (128 thr x 8 halves)
__global__ void softmax1024_kernel(const __half* __restrict__ attnl, __half* __restrict__ attnh) {
    const uint4* p = (const uint4*)(attnl + (long)blockIdx.x * 1024);
    uint4* ph = (uint4*)(attnh + (long)blockIdx.x * 1024);
    const int t = threadIdx.x;

    float2 f[4];
    {
        const uint4 u = p[t];
        f[0] = __half22float2(*(const __half2*)&u.x);
        f[1] = __half22float2(*(const __half2*)&u.y);
        f[2] = __half22float2(*(const __half2*)&u.z);
        f[3] = __half22float2(*(const __half2*)&u.w);
    }

    float m = -1e30f;
#pragma unroll
    for (int q = 0; q < 4; q++) m = fmaxf(m, fmaxf(f[q].x, f[q].y));
#pragma unroll
    for (int o = 16; o > 0; o >>= 1) m = fmaxf(m, __shfl_xor_sync(0xffffffffu, m, o));
    __shared__ float sm_[4], ss[4];
    if ((t & 31) == 0) sm_[t >> 5] = m;
    __syncthreads();
    m = fmaxf(fmaxf(sm_[0], sm_[1]), fmaxf(sm_[2], sm_[3]));

    float s = 0.f;
#pragma unroll
    for (int q = 0; q < 4; q++) {
        f[q].x = __expf(f[q].x - m); f[q].y = __expf(f[q].y - m);
        s += f[q].x + f[q].y;
    }
#pragma unroll
    for (int o = 16; o > 0; o >>= 1) s += __shfl_xor_sync(0xffffffffu, s, o);
    if ((t & 31) == 0) ss[t >> 5] = s;
    __syncthreads();
    s = ss[0] + ss[1] + ss[2] + ss[3];
    const float inv = 1.0f / s;

    uint4 o0;
    *(__half2*)&o0.x = __floats2half2_rn(f[0].x * inv, f[0].y * inv);
    *(__half2*)&o0.y = __floats2half2_rn(f[1].x * inv, f[1].y * inv);
    *(__half2*)&o0.z = __floats2half2_rn(f[2].x * inv, f[2].y * inv);
    *(__half2*)&o0.w = __floats2half2_rn(f[3].x * inv, f[3].y * inv);
    ph[t] = o0;
}

// ---------------- launch ----------------
extern "C" void kernel_launch(void* const* d_in, const int* in_sizes, int n_in,
                              void* d_out, int out_size) {
    const float* x          = (const float*)d_in[0];
    const float* qkv_w      = (const float*)d_in[1];
    const float* qkv_gamma  = (const float*)d_in[2];
    const float* qkv_beta   = (const float*)d_in[3];
    const float* qkv_mean   = (const float*)d_in[4];
    const float* qkv_var    = (const float*)d_in[5];
    const float* pos_bias   = (const float*)d_in[6];
    const float* proj_w     = (const float*)d_in[7];
    const float* proj_gamma = (const float*)d_in[8];
    const float* proj_beta  = (const float*)d_in[9];
    const float* proj_mean  = (const float*)d_in[10];
    const float* proj_var   = (const float*)d_in[11];
    float* out = (float*)d_out;

    __half *qkvh, *attnl, *attnh, *aoh, *vth, *xh, *wh, *pwh, *pbh;
    float *qs, *qh, *ps, *ph;
    cudaGetSymbolAddress((void**)&qkvh,  g_qkvh);
    cudaGetSymbolAddress((void**)&attnl, g_attnl);
    cudaGetSymbolAddress((void**)&attnh, g_attnh);
    cudaGetSymbolAddress((void**)&aoh,   g_aoh);
    cudaGetSymbolAddress((void**)&vth,   g_vth);
    cudaGetSymbolAddress((void**)&xh,    g_xh);
    cudaGetSymbolAddress((void**)&wh,    g_wh);
    cudaGetSymbolAddress((void**)&pwh,   g_pwh);
    cudaGetSymbolAddress((void**)&pbh,   g_pbh);
    cudaGetSymbolAddress((void**)&qs,    g_qs);
    cudaGetSymbolAddress((void**)&qh,    g_qh);
    cudaGetSymbolAddress((void**)&ps,    g_ps);
    cudaGetSymbolAddress((void**)&ph,    g_ph);

    cudaFuncSetAttribute(hgemm_kernel<0>, cudaFuncAttributeMaxDynamicSharedMemorySize, SMEM_BYTES);
    cudaFuncSetAttribute(hgemm_kernel<1>, cudaFuncAttributeMaxDynamicSharedMemorySize, SMEM_BYTES);
    cudaFuncSetAttribute(hgemm_kernel<2>, cudaFuncAttributeMaxDynamicSharedMemorySize, SMEM_BYTES);
    cudaFuncSetAttribute(hgemm_kernel<3>, cudaFuncAttributeMaxDynamicSharedMemorySize, SMEM_BYTES);

    bn_prep_kernel<<<(int)((QKVC + 255) / 256), 256>>>(qkv_gamma, qkv_beta, qkv_mean, qkv_var, qs, qh, (int)QKVC);
    f2h_kernel<<<(int)((MTOK * CIN / 8 + 255) / 256), 256>>>(x, xh, MTOK * CIN);
    f2h_kernel<<<(int)((QKVC * CIN / 8 + 255) / 256), 256>>>(qkv_w, wh, QKVC * CIN);

    const long perB = (long)N_ * QKVC;
    const long NN   = (long)N_ * N_;

    // 1) qkvh = half(BN(x @ qkv_w^T))   [16384 x 8192], K=768
    hgemm_kernel<0><<<dim3(QKVC / 128, MTOK / 128, 1), 256, SMEM_BYTES>>>(
        xh, CIN, 0, 0,
        wh, CIN, 0, 0,
        qkvh, QKVC, 0, 0,
        CIN, 1, qs, qh, nullptr, 0.f, 0, 0);

    f2h_kernel<<<(int)(((long)DOUT * NHV / 8 + 255) / 256), 256>>>(proj_w, pwh, (long)DOUT * NHV);
    f2h_kernel<<<(int)(((long)H_ * NN / 8 + 255) / 256), 256>>>(pos_bias, pbh, (long)H_ * NN);
    bn_prep_kernel<<<(DOUT + 255) / 256, 256>>>(proj_gamma, proj_beta, proj_mean, proj_var, ps, ph, DOUT);

    // 1b) V transpose (half)
    transpose_v_kernel<<<dim3(N_ / 32, VD_ / 32, B_ * H_), dim3(32, 8)>>>(qkvh, vth);

    // 2) half logits = q @ k^T * SCALE + pos_bias[h]   per (b,h): [1024 x 1024], K=256
    hgemm_kernel<1><<<dim3(N_ / 128, N_ / 128, B_ * H_), 256, SMEM_BYTES>>>(
        qkvh,       QKVC, perB, 1024,
        qkvh + 256, QKVC, perB, 1024,
        attnl, N_, 8 * NN, NN,
        KQ_, H_, nullptr, nullptr, pbh, SCALE_, NN, N_);

    // 3) softmax (half in, half out)
    softmax1024_kernel<<<(unsigned)(B_ * H_ * N_), 128>>>(attnl, attnh);

    // 4) aoh = half(clip(attnh @ vth^T)) per (b,h): [1024 x 512], K=1024
    hgemm_kernel<2><<<dim3(VD_ / 128, N_ / 128, B_ * H_), 256, SMEM_BYTES>>>(
        attnh, N_, 8 * NN, NN,
        vth, N_, 8L * VD_ * N_, (long)VD_ * N_,
        aoh, NHV, (long)N_ * NHV, VD_,
        N_, H_, nullptr, nullptr, nullptr, 0.f, 0, 0);

    // 5) out = BN(aoh @ proj_w^T)   [16384 x 512], K=4096
    hgemm_kernel<3><<<dim3(DOUT / 128, MTOK / 128, 1), 256, SMEM_BYTES>>>(
        aoh, NHV, 0, 0,
        pwh, NHV, 0, 0,
        out, DOUT, 0, 0,
        (int)NHV, 1, ps, ph, nullptr, 0.f, 0, 0);
}

// round 15
// speedup vs baseline: 1.5192x; 1.0017x over previous
#include <cuda_runtime.h>
#include <cuda_fp16.h>
#include <cstdint>

// ---------------- problem constants ----------------
constexpr int  B_    = 16;
constexpr int  N_    = 1024;
constexpr int  CIN   = 768;
constexpr int  H_    = 8;
constexpr int  KQ_   = 256;
constexpr int  VD_   = 512;
constexpr long MTOK  = 16384;
constexpr long QKVC  = 8192;
constexpr long NHV   = 4096;
constexpr int  DOUT  = 512;
constexpr float SCALE_ = 0.04419417382415922f;     // 512^-0.5
constexpr float EPS_   = 1e-5f;

// ---------------- scratch (device globals) ----------------
__device__ __half g_qkvh [MTOK * QKVC];
__device__ __half g_attnl[(long)B_ * H_ * N_ * N_];   // half logits
__device__ __half g_attnh[(long)B_ * H_ * N_ * N_];   // half probs
__device__ __half g_aoh  [MTOK * NHV];
__device__ __half g_vth  [(long)B_ * H_ * VD_ * N_];
__device__ __half g_xh   [MTOK * CIN];
__device__ __half g_wh   [QKVC * CIN];
__device__ __half g_pwh  [(long)DOUT * NHV];
__device__ __half g_pbh  [(long)H_ * N_ * N_];        // half pos_bias
__device__ float  g_qs[QKVC], g_qh[QKVC];
__device__ float  g_ps[DOUT], g_ph[DOUT];

// ---------------- helpers ----------------
__device__ __forceinline__ void cp16(uint32_t s, const void* g) {
    asm volatile("cp.async.cg.shared.global [%0], [%1], 16;"
                 :: "r"(s), "l"(__cvta_generic_to_global(g)));
}
__device__ __forceinline__ uint32_t smem_u32(const void* p) {
    uint32_t a;
    asm("{ .reg .u64 t; cvta.to.shared.u64 t, %1; cvt.u32.u64 %0, t; }" : "=r"(a) : "l"(p));
    return a;
}
__device__ __forceinline__ void mma_f16(float* c, const uint32_t* a, uint32_t b0, uint32_t b1) {
    asm volatile(
        "mma.sync.aligned.m16n8k16.row.col.f32.f16.f16.f32 "
        "{%0,%1,%2,%3}, {%4,%5,%6,%7}, {%8,%9}, {%0,%1,%2,%3};"
        : "+f"(c[0]), "+f"(c[1]), "+f"(c[2]), "+f"(c[3])
        : "r"(a[0]), "r"(a[1]), "r"(a[2]), "r"(a[3]), "r"(b0), "r"(b1));
}
__device__ __forceinline__ void ldsm4(uint32_t* r, uint32_t a) {
    asm volatile("ldmatrix.sync.aligned.m8n8.x4.shared.b16 {%0,%1,%2,%3}, [%4];"
                 : "=r"(r[0]), "=r"(r[1]), "=r"(r[2]), "=r"(r[3]) : "r"(a));
}

// ---------------- fp16 mma GEMM: tile 128x128, K-chunk 64, 3-stage, occ 2 -------------
// A: [M][K] K-contig half. B: [N][K] K-contig half (C = A * B^T).
// MODE 0: half(BN)  1: half(alpha*acc + half bias)  2: half(clamp(-1,1))  3: fp32 BN
constexpr int LDT   = 36;
constexpr int ROWB  = LDT * 4;              // 144 bytes per row
constexpr int CH    = 128 * LDT;
constexpr int CHB   = CH * 4;               // 18432 bytes per tile buffer
constexpr int NST   = 3;
constexpr int SMEM_BYTES = 2 * NST * CHB;   // 110592 B -> 2 CTAs/SM

template<int MODE>
__global__ __launch_bounds__(256, 2)
void hgemm_kernel(const __half* __restrict__ Aall, long lda, long aos, long ais,
                  const __half* __restrict__ Ball, long ldb, long bos, long bis,
                  void* __restrict__ Call, long ldc, long cosz, long cis,
                  int K, int zdiv,
                  const float* __restrict__ p0, const float* __restrict__ p1,
                  const __half* __restrict__ pbh,
                  float alpha, long bias_is, long ldbias)
{
    extern __shared__ uint32_t smw[];
    const uint32_t sbase = smem_u32(smw);

    const int tid = threadIdx.x;
    const int wid = tid >> 5, lane = tid & 31;
    const int wm = wid & 1, wn = wid >> 1;
    const int rg = lane >> 2, lg = lane & 3;

    const int z  = blockIdx.z;
    const int zo = z / zdiv, zi = z - zo * zdiv;
    const __half* A  = Aall + (long)zo * aos + (long)zi * ais;
    const __half* Bp = Ball + (long)zo * bos + (long)zi * bis;
    const long m0 = (long)blockIdx.y * 128;
    const long n0 = (long)blockIdx.x * 128;

    float acc[4][4][4];
#pragma unroll
    for (int i = 0; i < 4; i++)
#pragma unroll
        for (int j = 0; j < 4; j++)
#pragma unroll
            for (int q = 0; q < 4; q++) acc[i][j][q] = 0.f;

    auto load_tile = [&](const __half* src, long ld, int kc, uint32_t bufByteOff) {
        const __half* s = src + (long)kc * 64;
#pragma unroll
        for (int i = 0; i < 4; i++) {
            int idx = tid + i * 256;
            int r = idx >> 3, c = idx & 7;
            cp16(sbase + bufByteOff + (uint32_t)(r * ROWB + c * 16),
                 s + (long)r * ld + c * 8);
        }
    };

    const __half* Abase = A + m0 * lda;
    const __half* Bbase = Bp + n0 * ldb;

    const uint32_t aOff = (uint32_t)((wm * 64 + (lane & 15)) * ROWB + ((lane >> 4) & 1) * 16);
    const uint32_t bOff = (uint32_t)((wn * 32 + ((lane >> 4) & 1) * 8 + (lane & 7)) * ROWB
                                     + ((lane >> 3) & 1) * 16);

    const int nch = K >> 6;
    load_tile(Abase, lda, 0, 0);
    load_tile(Bbase, ldb, 0, NST * CHB);
    asm volatile("cp.async.commit_group;");
    load_tile(Abase, lda, 1, CHB);
    load_tile(Bbase, ldb, 1, NST * CHB + CHB);
    asm volatile("cp.async.commit_group;");

    int st = 0;
    for (int kc = 0; kc < nch; kc++) {
        if (kc + 1 < nch) asm volatile("cp.async.wait_group 1;");
        else              asm volatile("cp.async.wait_group 0;");
        __syncthreads();

        const bool pf = (kc + 2 < nch);
        int s2 = st + 2; if (s2 >= NST) s2 -= NST;
        const uint32_t aPB = sbase + (uint32_t)(s2 * CHB);
        const uint32_t bPB = sbase + (uint32_t)(NST * CHB + s2 * CHB);
        const __half* aPS = Abase + (long)(kc + 2) * 64;
        const __half* bPS = Bbase + (long)(kc + 2) * 64;

        const uint32_t aStage = sbase + st * CHB + aOff;
        const uint32_t bStage = sbase + NST * CHB + st * CHB + bOff;

        // fragments for ks = 0
        uint32_t a[4][4], bfr[2][4];
#pragma unroll
        for (int i = 0; i < 4; i++) ldsm4(a[i], aStage + i * (16 * ROWB));
        ldsm4(bfr[0], bStage);
        ldsm4(bfr[1], bStage + 16 * ROWB);

#pragma unroll
        for (int ks = 0; ks < 4; ks++) {
            // spread gmem->smem prefetch (2 cp.async per ks)
            if (pf) {
                int idx = tid + ks * 256;
                int r = idx >> 3, c = idx & 7;
                cp16(aPB + (uint32_t)(r * ROWB + c * 16), aPS + (long)r * lda + c * 8);
                cp16(bPB + (uint32_t)(r * ROWB + c * 16), bPS + (long)r * ldb + c * 8);
            }
            // j-pair 0 consumes bfr[0]
#pragma unroll
            for (int i = 0; i < 4; i++) {
                mma_f16(acc[i][0], a[i], bfr[0][0], bfr[0][1]);
                mma_f16(acc[i][1], a[i], bfr[0][2], bfr[0][3]);
            }
            if (ks < 3) ldsm4(bfr[0], bStage + (ks + 1) * 32);               // rotate in place
            // j-pair 1 consumes bfr[1]
#pragma unroll
            for (int i = 0; i < 4; i++) {
                mma_f16(acc[i][2], a[i], bfr[1][0], bfr[1][1]);
                mma_f16(acc[i][3], a[i], bfr[1][2], bfr[1][3]);
            }
            if (ks < 3) {
                ldsm4(bfr[1], bStage + 16 * ROWB + (ks + 1) * 32);
#pragma unroll
                for (int i = 0; i < 4; i++)
                    ldsm4(a[i], aStage + i * (16 * ROWB) + (ks + 1) * 32);
            }
        }
        if (pf) asm volatile("cp.async.commit_group;");
        st++; if (st >= NST) st = 0;
    }

    // -------- epilogue --------
    const long cr0 = m0 + wm * 64 + rg;
    const long cn0 = n0 + wn * 32 + 2 * lg;
#pragma unroll
    for (int i = 0; i < 4; i++) {
        const long r0 = cr0 + i * 16, r1 = r0 + 8;
#pragma unroll
        for (int j = 0; j < 4; j++) {
            const long cc = cn0 + j * 8;
            float v0 = acc[i][j][0], v1 = acc[i][j][1];
            float v2 = acc[i][j][2], v3 = acc[i][j][3];
            if (MODE == 0 || MODE == 3) {
                const float s0 = p0[cc], s1 = p0[cc + 1];
                const float h0 = p1[cc], h1 = p1[cc + 1];
                v0 = fmaf(v0, s0, h0); v1 = fmaf(v1, s1, h1);
                v2 = fmaf(v2, s0, h0); v3 = fmaf(v3, s1, h1);
            } else if (MODE == 1) {
                const __half* bias = pbh + (long)zi * bias_is;
                const float2 b0 = __half22float2(*(const __half2*)(bias + r0 * ldbias + cc));
                const float2 b1 = __half22float2(*(const __half2*)(bias + r1 * ldbias + cc));
                v0 = fmaf(v0, alpha, b0.x); v1 = fmaf(v1, alpha, b0.y);
                v2 = fmaf(v2, alpha, b1.x); v3 = fmaf(v3, alpha, b1.y);
            } else {
                v0 = fminf(fmaxf(v0, -1.f), 1.f);
                v1 = fminf(fmaxf(v1, -1.f), 1.f);
                v2 = fminf(fmaxf(v2, -1.f), 1.f);
                v3 = fminf(fmaxf(v3, -1.f), 1.f);
            }
            if (MODE != 3) {
                __half* Ch = (__half*)Call + (long)zo * cosz + (long)zi * cis;
                *(__half2*)(Ch + r0 * ldc + cc) = __floats2half2_rn(v0, v1);
                *(__half2*)(Ch + r1 * ldc + cc) = __floats2half2_rn(v2, v3);
            } else {
                float* Cf = (float*)Call + (long)zo * cosz + (long)zi * cis;
                *(float2*)(Cf + r0 * ldc + cc) = make_float2(v0, v1);
                *(float2*)(Cf + r1 * ldc + cc) = make_float2(v2, v3);
            }
        }
    }
}

// ---------------- small kernels ----------------
__global__ void bn_prep_kernel(const float* __restrict__ g, const float* __restrict__ b,
                               const float* __restrict__ mu, const float* __restrict__ var,
                               float* __restrict__ sc, float* __restrict__ sh, int n) {
    int i = blockIdx.x * blockDim.x + threadIdx.x;
    if (i < n) {
        float s = g[i] * rsqrtf(var[i] + EPS_);
        sc[i] = s;
        sh[i] = b[i] - mu[i] * s;
    }
}

__global__ void f2h_kernel(const float* __restrict__ in, __half* __restrict__ out, long n) {
    long i = ((long)blockIdx.x * blockDim.x + threadIdx.x) * 8;
    if (i < n) {
        float4 v0 = *(const float4*)(in + i);
        float4 v1 = *(const float4*)(in + i + 4);
        __half2* o = (__half2*)(out + i);
        o[0] = __floats2half2_rn(v0.x, v0.y);
        o[1] = __floats2half2_rn(v0.z, v0.w);
        o[2] = __floats2half2_rn(v1.x, v1.y);
        o[3] = __floats2half2_rn(v1.z, v1.w);
    }
}

// V transpose: qkvh[b,n][h*1024+512+d] -> vth[(b*8+h)*512+d][n]
__global__ void transpose_v_kernel(const __half* __restrict__ qkv, __half* __restrict__ vt) {
    __shared__ __half t[32][33];
    const int z = blockIdx.z, b = z >> 3, h = z & 7;
    const long n0 = (long)blockIdx.x * 32, d0 = (long)blockIdx.y * 32;
    const int tx = threadIdx.x, ty = threadIdx.y;
    const __half* src = qkv + (long)b * N_ * QKVC + (long)h * 1024 + 512;
#pragma unroll
    for (int i = 0; i < 32; i += 8)
        t[ty + i][tx] = src[(n0 + ty + i) * QKVC + d0 + tx];
    __syncthreads();
    __half* dst = vt + ((long)z * VD_ + d0) * N_ + n0;
#pragma unroll
    for (int i = 0; i < 32; i += 8)
        dst[(ty + i) * (long)N_ + tx] = t[tx][ty + i];
}

// rowwise softmax over 1024 half logits -> half probs (128 thr x 8 halves)
__global__ void softmax1024_kernel(const __half* __restrict__ attnl, __half* __restrict__ attnh) {
    const uint4* p = (const uint4*)(attnl + (long)blockIdx.x * 1024);
    uint4* ph = (uint4*)(attnh + (long)blockIdx.x * 1024);
    const int t = threadIdx.x;

    float2 f[4];
    {
        const uint4 u = p[t];
        f[0] = __half22float2(*(const __half2*)&u.x);
        f[1] = __half22float2(*(const __half2*)&u.y);
        f[2] = __half22float2(*(const __half2*)&u.z);
        f[3] = __half22float2(*(const __half2*)&u.w);
    }

    float m = -1e30f;
#pragma unroll
    for (int q = 0; q < 4; q++) m = fmaxf(m, fmaxf(f[q].x, f[q].y));
#pragma unroll
    for (int o = 16; o > 0; o >>= 1) m = fmaxf(m, __shfl_xor_sync(0xffffffffu, m, o));
    __shared__ float sm_[4], ss[4];
    if ((t & 31) == 0) sm_[t >> 5] = m;
    __syncthreads();
    m = fmaxf(fmaxf(sm_[0], sm_[1]), fmaxf(sm_[2], sm_[3]));

    float s = 0.f;
#pragma unroll
    for (int q = 0; q < 4; q++) {
        f[q].x = __expf(f[q].x - m); f[q].y = __expf(f[q].y - m);
        s += f[q].x + f[q].y;
    }
#pragma unroll
    for (int o = 16; o > 0; o >>= 1) s += __shfl_xor_sync(0xffffffffu, s, o);
    if ((t & 31) == 0) ss[t >> 5] = s;
    __syncthreads();
    s = ss[0] + ss[1] + ss[2] + ss[3];
    const float inv = 1.0f / s;

    uint4 o0;
    *(__half2*)&o0.x = __floats2half2_rn(f[0].x * inv, f[0].y * inv);
    *(__half2*)&o0.y = __floats2half2_rn(f[1].x * inv, f[1].y * inv);
    *(__half2*)&o0.z = __floats2half2_rn(f[2].x * inv, f[2].y * inv);
    *(__half2*)&o0.w = __floats2half2_rn(f[3].x * inv, f[3].y * inv);
    ph[t] = o0;
}

// ---------------- launch ----------------
extern "C" void kernel_launch(void* const* d_in, const int* in_sizes, int n_in,
                              void* d_out, int out_size) {
    const float* x          = (const float*)d_in[0];
    const float* qkv_w      = (const float*)d_in[1];
    const float* qkv_gamma  = (const float*)d_in[2];
    const float* qkv_beta   = (const float*)d_in[3];
    const float* qkv_mean   = (const float*)d_in[4];
    const float* qkv_var    = (const float*)d_in[5];
    const float* pos_bias   = (const float*)d_in[6];
    const float* proj_w     = (const float*)d_in[7];
    const float* proj_gamma = (const float*)d_in[8];
    const float* proj_beta  = (const float*)d_in[9];
    const float* proj_mean  = (const float*)d_in[10];
    const float* proj_var   = (const float*)d_in[11];
    float* out = (float*)d_out;

    __half *qkvh, *attnl, *attnh, *aoh, *vth, *xh, *wh, *pwh, *pbh;
    float *qs, *qh, *ps, *ph;
    cudaGetSymbolAddress((void**)&qkvh,  g_qkvh);
    cudaGetSymbolAddress((void**)&attnl, g_attnl);
    cudaGetSymbolAddress((void**)&attnh, g_attnh);
    cudaGetSymbolAddress((void**)&aoh,   g_aoh);
    cudaGetSymbolAddress((void**)&vth,   g_vth);
    cudaGetSymbolAddress((void**)&xh,    g_xh);
    cudaGetSymbolAddress((void**)&wh,    g_wh);
    cudaGetSymbolAddress((void**)&pwh,   g_pwh);
    cudaGetSymbolAddress((void**)&pbh,   g_pbh);
    cudaGetSymbolAddress((void**)&qs,    g_qs);
    cudaGetSymbolAddress((void**)&qh,    g_qh);
    cudaGetSymbolAddress((void**)&ps,    g_ps);
    cudaGetSymbolAddress((void**)&ph,    g_ph);

    cudaFuncSetAttribute(hgemm_kernel<0>, cudaFuncAttributeMaxDynamicSharedMemorySize, SMEM_BYTES);
    cudaFuncSetAttribute(hgemm_kernel<1>, cudaFuncAttributeMaxDynamicSharedMemorySize, SMEM_BYTES);
    cudaFuncSetAttribute(hgemm_kernel<2>, cudaFuncAttributeMaxDynamicSharedMemorySize, SMEM_BYTES);
    cudaFuncSetAttribute(hgemm_kernel<3>, cudaFuncAttributeMaxDynamicSharedMemorySize, SMEM_BYTES);

    bn_prep_kernel<<<(int)((QKVC + 255) / 256), 256>>>(qkv_gamma, qkv_beta, qkv_mean, qkv_var, qs, qh, (int)QKVC);
    f2h_kernel<<<(int)((MTOK * CIN / 8 + 255) / 256), 256>>>(x, xh, MTOK * CIN);
    f2h_kernel<<<(int)((QKVC * CIN / 8 + 255) / 256), 256>>>(qkv_w, wh, QKVC * CIN);

    const long perB = (long)N_ * QKVC;
    const long NN   = (long)N_ * N_;

    // 1) qkvh = half(BN(x @ qkv_w^T))   [16384 x 8192], K=768
    hgemm_kernel<0><<<dim3(QKVC / 128, MTOK / 128, 1), 256, SMEM_BYTES>>>(
        xh, CIN, 0, 0,
        wh, CIN, 0, 0,
        qkvh, QKVC, 0, 0,
        CIN, 1, qs, qh, nullptr, 0.f, 0, 0);

    f2h_kernel<<<(int)(((long)DOUT * NHV / 8 + 255) / 256), 256>>>(proj_w, pwh, (long)DOUT * NHV);
    f2h_kernel<<<(int)(((long)H_ * NN / 8 + 255) / 256), 256>>>(pos_bias, pbh, (long)H_ * NN);
    bn_prep_kernel<<<(DOUT + 255) / 256, 256>>>(proj_gamma, proj_beta, proj_mean, proj_var, ps, ph, DOUT);

    // 1b) V transpose (half)
    transpose_v_kernel<<<dim3(N_ / 32, VD_ / 32, B_ * H_), dim3(32, 8)>>>(qkvh, vth);

    // 2) half logits = q @ k^T * SCALE + pos_bias[h]   per (b,h): [1024 x 1024], K=256
    hgemm_kernel<1><<<dim3(N_ / 128, N_ / 128, B_ * H_), 256, SMEM_BYTES>>>(
        qkvh,       QKVC, perB, 1024,
        qkvh + 256, QKVC, perB, 1024,
        attnl, N_, 8 * NN, NN,
        KQ_, H_, nullptr, nullptr, pbh, SCALE_, NN, N_);

    // 3) softmax (half in, half out)
    softmax1024_kernel<<<(unsigned)(B_ * H_ * N_), 128>>>(attnl, attnh);

    // 4) aoh = half(clip(attnh @ vth^T)) per (b,h): [1024 x 512], K=1024
    hgemm_kernel<2><<<dim3(VD_ / 128, N_ / 128, B_ * H_), 256, SMEM_BYTES>>>(
        attnh, N_, 8 * NN, NN,
        vth, N_, 8L * VD_ * N_, (long)VD_ * N_,
        aoh, NHV, (long)N_ * NHV, VD_,
        N_, H_, nullptr, nullptr, nullptr, 0.f, 0, 0);

    // 5) out = BN(aoh @ proj_w^T)   [16384 x 512], K=4096
    hgemm_kernel<3><<<dim3(DOUT / 128, MTOK / 128, 1), 256, SMEM_BYTES>>>(
        aoh, NHV, 0, 0,
        pwh, NHV, 0, 0,
        out, DOUT, 0, 0,
        (int)NHV, 1, ps, ph, nullptr, 0.f, 0, 0);
}